// round 9
// baseline (speedup 1.0000x reference)
#include <cuda_runtime.h>
#include <cuda_fp16.h>
#include <cstdint>

#define B_DIM 4
#define C_DIM 128
#define L_DIM 24
#define HW_DIM 4096

#define NTHREADS 512

// All SMEM buffers: 128 rows x 256B, XOR-swizzled (16B chunk ^ row&7). 32KB each.
#define SM_M    0
#define SM_W    32768
#define SM_BH   65536
#define SM_BX0H 98304
#define SM_BX0L 131072
#define SM_BX1H 163840
#define SM_BX1L 196608
#define SMEM_BYTES 229376

__device__ __align__(16) float g_M[C_DIM * C_DIM];             // (U@V)[c][k]
__device__ __align__(16) float g_decay[B_DIM * L_DIM * C_DIM]; // exp(-softplus(lam)*dt)

// ---------------- helpers ----------------
__device__ __forceinline__ uint32_t smem_u32(const void* p) {
    uint32_t a;
    asm("{ .reg .u64 t; cvta.to.shared.u64 t, %1; cvt.u32.u64 %0, t; }" : "=r"(a) : "l"(p));
    return a;
}
// swizzled byte offset for (row r, byte-in-row cb), 256B rows
__device__ __forceinline__ uint32_t swz(int r, int cb) {
    return (uint32_t)((r << 8) + ((((cb >> 4) ^ (r & 7)) << 4)) + (cb & 15));
}
__device__ __forceinline__ void ldsm4(uint32_t* r, uint32_t a) {
    asm volatile("ldmatrix.sync.aligned.m8n8.x4.shared.b16 {%0,%1,%2,%3}, [%4];"
                 : "=r"(r[0]), "=r"(r[1]), "=r"(r[2]), "=r"(r[3]) : "r"(a));
}
__device__ __forceinline__ void ldsm4t(uint32_t* r, uint32_t a) {
    asm volatile("ldmatrix.sync.aligned.m8n8.x4.trans.shared.b16 {%0,%1,%2,%3}, [%4];"
                 : "=r"(r[0]), "=r"(r[1]), "=r"(r[2]), "=r"(r[3]) : "r"(a));
}
__device__ __forceinline__ void mma16816(float* d, const uint32_t* a, const uint32_t* b) {
    asm volatile("mma.sync.aligned.m16n8k16.row.col.f32.f16.f16.f32 "
                 "{%0,%1,%2,%3}, {%4,%5,%6,%7}, {%8,%9}, {%0,%1,%2,%3};"
                 : "+f"(d[0]), "+f"(d[1]), "+f"(d[2]), "+f"(d[3])
                 : "r"(a[0]), "r"(a[1]), "r"(a[2]), "r"(a[3]), "r"(b[0]), "r"(b[1]));
}
__device__ __forceinline__ void split2h(float x0, float x1, uint32_t& hi, uint32_t& lo) {
    asm("cvt.rn.f16x2.f32 %0, %1, %2;" : "=r"(hi) : "f"(x1), "f"(x0));
    float2 hf = __half22float2(*reinterpret_cast<__half2*>(&hi));
    float r0 = x0 - hf.x;
    float r1 = x1 - hf.y;
    asm("cvt.rn.f16x2.f32 %0, %1, %2;" : "=r"(lo) : "f"(r1), "f"(r0));
}
__device__ __forceinline__ uint32_t pack_h2(float x0, float x1) {
    uint32_t r;
    asm("cvt.rn.f16x2.f32 %0, %1, %2;" : "=r"(r) : "f"(x1), "f"(x0));
    return r;
}
__device__ __forceinline__ float2 join2h(uint32_t hi, uint32_t lo) {
    float2 a = __half22float2(*reinterpret_cast<__half2*>(&hi));
    float2 b = __half22float2(*reinterpret_cast<__half2*>(&lo));
    return make_float2(a.x + b.x, a.y + b.y);
}

// ---------------- precompute ----------------
__global__ void precompute_kernel(const float* __restrict__ lam,
                                  const float* __restrict__ U,
                                  const float* __restrict__ V,
                                  const float* __restrict__ listT) {
    int tid = threadIdx.x;
    if (blockIdx.x < 64) {
        int e = blockIdx.x * 256 + tid;
        int c = e >> 7, k = e & 127;
        float s0 = 0.f, s1 = 0.f;
        #pragma unroll 8
        for (int r = 0; r < 64; r += 2) {
            s0 += U[c * 64 + r] * V[r * C_DIM + k];
            s1 += U[c * 64 + r + 1] * V[(r + 1) * C_DIM + k];
        }
        g_M[e] = s0 + s1;
    } else {
        int idx = (blockIdx.x - 64) * 256 + tid;
        if (idx < B_DIM * L_DIM * C_DIM) {
            int c = idx & 127;
            int t = (idx >> 7) % L_DIM;
            int b = idx / (L_DIM * C_DIM);
            float sp = log1pf(expf(lam[c]));
            g_decay[idx] = expf(-sp * listT[b * L_DIM + t]);
        }
    }
}

// single-pass fp16 GEMM, k=128, swizzled buffers: acc += A[m0..+32][k]*B[k][n0..+32]
__device__ __forceinline__ void gemm128(uint32_t aB, uint32_t bB,
                                        int m0, int n0, int lane,
                                        float acc[2][4][4]) {
    const int arow = lane & 15;
    const int aq   = lane >> 4;
    #pragma unroll
    for (int k = 0; k < 128; k += 16) {
        uint32_t ah[2][4];
        #pragma unroll
        for (int mt = 0; mt < 2; ++mt) {
            int r = m0 + mt * 16 + arow;
            ldsm4(ah[mt], aB + swz(r, k * 2 + aq * 16));
        }
        #pragma unroll
        for (int ng = 0; ng < 2; ++ng) {
            int r = k + arow;
            uint32_t bv[4];
            ldsm4t(bv, bB + swz(r, (n0 + ng * 16) * 2 + aq * 16));
            #pragma unroll
            for (int hh = 0; hh < 2; ++hh) {
                const int nt = ng * 2 + hh;
                mma16816(acc[0][nt], ah[0], bv + hh * 2);
                mma16816(acc[1][nt], ah[1], bv + hh * 2);
            }
        }
    }
}

// ---------------- main kernel ----------------
__global__ __launch_bounds__(NTHREADS, 1)
void recurrent_kernel(const float* __restrict__ x,
                      const float* __restrict__ h0,
                      const float* __restrict__ Wout,
                      float* __restrict__ out,
                      float* __restrict__ hfin) {
    extern __shared__ char smem[];
    const uint32_t sb = smem_u32(smem);

    const int tid  = threadIdx.x;
    const int lane = tid & 31;
    const int wid  = tid >> 5;            // 0..15
    const int b    = blockIdx.x >> 5;
    const int s0   = (blockIdx.x & 31) * 128;
    const int wm   = wid & 3;
    const int wn   = wid >> 2;
    const int m0   = wm * 32;
    const int n0   = wn * 32;
    const int g    = lane >> 2;
    const int tq   = lane & 3;
    const size_t rstride = (size_t)L_DIM * HW_DIM;

    // ---- stationary weights (fp16), swizzled ----
    for (int e = tid; e < C_DIM * C_DIM; e += NTHREADS) {
        int r = e >> 7, k = e & 127;
        uint32_t off = swz(r, k * 2);
        *(__half*)(smem + SM_M + off) = __float2half_rn(g_M[e]);
        *(__half*)(smem + SM_W + off) = __float2half_rn(Wout[e]);
    }

    // ---- initial hidden state fragments ----
    float h[2][4][4];
    #pragma unroll
    for (int mt = 0; mt < 2; ++mt) {
        #pragma unroll
        for (int nt = 0; nt < 4; ++nt) {
            int c_lo = m0 + mt * 16 + g;
            int s    = s0 + n0 + nt * 8 + tq * 2;
            float2 v0 = *(const float2*)&h0[(size_t)(b * C_DIM + c_lo) * HW_DIM + s];
            float2 v1 = *(const float2*)&h0[(size_t)(b * C_DIM + c_lo + 8) * HW_DIM + s];
            h[mt][nt][0] = v0.x; h[mt][nt][1] = v0.y;
            h[mt][nt][2] = v1.x; h[mt][nt][3] = v1.y;
        }
    }

    // ---- prefetch x(0) into regs ----
    const int sr  = wid;            // staging row base (stride 16)
    const int sc4 = lane;           // float4 column
    float4 xr[8];
    #pragma unroll
    for (int it = 0; it < 8; ++it) {
        int r = it * 16 + sr;
        xr[it] = *(const float4*)(x + ((size_t)(b * C_DIM + r) * L_DIM + 0) * HW_DIM
                                    + s0 + sc4 * 4);
    }
    __syncthreads();   // weights staged (also covers h0 loads; not strictly needed)

    // ---- pre-loop: stage x(0) into BX0, prefetch x(1) ----
    #pragma unroll
    for (int it = 0; it < 8; ++it) {
        int r = it * 16 + sr;
        float4 v = xr[it];
        uint32_t h0p, l0p, h1p, l1p;
        split2h(v.x, v.y, h0p, l0p);
        split2h(v.z, v.w, h1p, l1p);
        uint32_t off = swz(r, sc4 * 8);
        *(uint2*)(smem + SM_BX0H + off) = make_uint2(h0p, h1p);
        *(uint2*)(smem + SM_BX0L + off) = make_uint2(l0p, l1p);
    }
    #pragma unroll
    for (int it = 0; it < 8; ++it) {
        int r = it * 16 + sr;
        xr[it] = *(const float4*)(x + ((size_t)(b * C_DIM + r) * L_DIM + 1) * HW_DIM
                                    + s0 + sc4 * 4);
    }
    __syncthreads();   // BX0 visible

    for (int t = 0; t < L_DIM; ++t) {
        const uint32_t bxh = sb + (uint32_t)((t & 1) ? SM_BX1H : SM_BX0H);
        const uint32_t bxl = bxh + 32768;
        const uint32_t nbxh = sb + (uint32_t)((t & 1) ? SM_BX0H : SM_BX1H);
        const uint32_t nbxl = nbxh + 32768;

        // ---- GEMM1: u = M @ x(t) ----
        float acc[2][4][4];
        #pragma unroll
        for (int mt = 0; mt < 2; ++mt)
            #pragma unroll
            for (int nt = 0; nt < 4; ++nt)
                #pragma unroll
                for (int q = 0; q < 4; ++q) acc[mt][nt][q] = 0.f;
        gemm128(sb + SM_M, bxh, m0, n0, lane, acc);

        // ---- recurrence: h = decay(c)*h + u ----
        {
            const float* dk = &g_decay[(b * L_DIM + t) * C_DIM];
            #pragma unroll
            for (int mt = 0; mt < 2; ++mt) {
                float dA = __ldg(&dk[m0 + mt * 16 + g]);
                float dB = __ldg(&dk[m0 + mt * 16 + 8 + g]);
                #pragma unroll
                for (int nt = 0; nt < 4; ++nt) {
                    h[mt][nt][0] = dA * h[mt][nt][0] + acc[mt][nt][0];
                    h[mt][nt][1] = dA * h[mt][nt][1] + acc[mt][nt][1];
                    h[mt][nt][2] = dB * h[mt][nt][2] + acc[mt][nt][2];
                    h[mt][nt][3] = dB * h[mt][nt][3] + acc[mt][nt][3];
                }
            }
        }

        // ---- residual x(t) from BX (hi+lo) into GEMM2 accumulators ----
        #pragma unroll
        for (int mt = 0; mt < 2; ++mt) {
            #pragma unroll
            for (int nt = 0; nt < 4; ++nt) {
                int c_lo = m0 + mt * 16 + g;
                int cb   = (n0 + nt * 8 + tq * 2) * 2;
                uint32_t o0 = swz(c_lo, cb);
                uint32_t o1 = swz(c_lo + 8, cb);
                float2 r0 = join2h(*(const uint32_t*)(bxh - sb + smem + o0),
                                   *(const uint32_t*)(bxl - sb + smem + o0));
                float2 r1 = join2h(*(const uint32_t*)(bxh - sb + smem + o1),
                                   *(const uint32_t*)(bxl - sb + smem + o1));
                acc[mt][nt][0] = r0.x; acc[mt][nt][1] = r0.y;
                acc[mt][nt][2] = r1.x; acc[mt][nt][3] = r1.y;
            }
        }

        // ---- stage x(t+1) into ALT buffer (off critical path) ----
        #pragma unroll
        for (int it = 0; it < 8; ++it) {
            int r = it * 16 + sr;
            float4 v = xr[it];
            uint32_t h0p, l0p, h1p, l1p;
            split2h(v.x, v.y, h0p, l0p);
            split2h(v.z, v.w, h1p, l1p);
            uint32_t off = swz(r, sc4 * 8);
            *(uint2*)(nbxh - sb + smem + off) = make_uint2(h0p, h1p);
            *(uint2*)(nbxl - sb + smem + off) = make_uint2(l0p, l1p);
        }
        // ---- prefetch x(t+2) ----
        {
            int tn = (t + 2 < L_DIM) ? t + 2 : L_DIM - 1;
            #pragma unroll
            for (int it = 0; it < 8; ++it) {
                int r = it * 16 + sr;
                xr[it] = *(const float4*)(x + ((size_t)(b * C_DIM + r) * L_DIM + tn) * HW_DIM
                                            + s0 + sc4 * 4);
            }
        }

        // ---- write h (f16) into BH for GEMM2 ----
        #pragma unroll
        for (int mt = 0; mt < 2; ++mt) {
            #pragma unroll
            for (int nt = 0; nt < 4; ++nt) {
                int c_lo = m0 + mt * 16 + g;
                int cb   = (n0 + nt * 8 + tq * 2) * 2;
                *(uint32_t*)(smem + SM_BH + swz(c_lo, cb))     = pack_h2(h[mt][nt][0], h[mt][nt][1]);
                *(uint32_t*)(smem + SM_BH + swz(c_lo + 8, cb)) = pack_h2(h[mt][nt][2], h[mt][nt][3]);
            }
        }
        __syncthreads();   // BH + next-x buffer visible

        // ---- GEMM2: out = x + Wout @ h ----
        gemm128(sb + SM_W, sb + SM_BH, m0, n0, lane, acc);

        // ---- store output ----
        #pragma unroll
        for (int mt = 0; mt < 2; ++mt) {
            #pragma unroll
            for (int nt = 0; nt < 4; ++nt) {
                int d_lo = m0 + mt * 16 + g;
                float* po = out + ((size_t)(b * C_DIM + d_lo) * L_DIM + t) * HW_DIM
                                + s0 + n0 + nt * 8 + tq * 2;
                *(float2*)po = make_float2(acc[mt][nt][0], acc[mt][nt][1]);
                *(float2*)(po + 8 * rstride) = make_float2(acc[mt][nt][2], acc[mt][nt][3]);
            }
        }
        __syncthreads();   // all BH reads done before next step's h-write
    }

    // ---- final hidden state ----
    #pragma unroll
    for (int mt = 0; mt < 2; ++mt) {
        #pragma unroll
        for (int nt = 0; nt < 4; ++nt) {
            int c_lo = m0 + mt * 16 + g;
            int s    = s0 + n0 + nt * 8 + tq * 2;
            *(float2*)&hfin[(size_t)(b * C_DIM + c_lo) * HW_DIM + s] =
                make_float2(h[mt][nt][0], h[mt][nt][1]);
            *(float2*)&hfin[(size_t)(b * C_DIM + c_lo + 8) * HW_DIM + s] =
                make_float2(h[mt][nt][2], h[mt][nt][3]);
        }
    }
}

extern "C" void kernel_launch(void* const* d_in, const int* in_sizes, int n_in,
                              void* d_out, int out_size) {
    const float* x     = (const float*)d_in[0];
    const float* h0    = (const float*)d_in[1];
    const float* listT = (const float*)d_in[2];
    const float* lam   = (const float*)d_in[3];
    const float* U     = (const float*)d_in[4];
    const float* V     = (const float*)d_in[5];
    const float* Wout  = (const float*)d_in[6];

    float* out  = (float*)d_out;
    float* hfin = out + (size_t)B_DIM * C_DIM * L_DIM * HW_DIM;

    precompute_kernel<<<112, 256>>>(lam, U, V, listT);

    cudaFuncSetAttribute(recurrent_kernel,
                         cudaFuncAttributeMaxDynamicSharedMemorySize, SMEM_BYTES);
    recurrent_kernel<<<B_DIM * (HW_DIM / 128), NTHREADS, SMEM_BYTES>>>(x, h0, Wout, out, hfin);
}

// round 10
// speedup vs baseline: 1.1582x; 1.1582x over previous
#include <cuda_runtime.h>
#include <cuda_fp16.h>
#include <cstdint>

#define B_DIM 4
#define C_DIM 128
#define L_DIM 24
#define HW_DIM 4096

#define NTHREADS 256
#define ROWW 272          // weight buffer row stride bytes (128 fp16 + pad)
#define ROWX 144          // x/h buffer row stride bytes (64 fp16 + pad)

#define SM_M  0           // 128*272 = 34816
#define SM_W  34816
#define SM_BX 69632       // 128*144 = 18432
#define SM_BH 88064
#define SMEM_BYTES 106496

__device__ __align__(16) float g_M[C_DIM * C_DIM];             // (U@V)[c][k]
__device__ __align__(16) float g_decay[B_DIM * L_DIM * C_DIM]; // exp(-softplus(lam)*dt)

// ---------------- helpers ----------------
__device__ __forceinline__ uint32_t smem_u32(const void* p) {
    uint32_t a;
    asm("{ .reg .u64 t; cvta.to.shared.u64 t, %1; cvt.u32.u64 %0, t; }" : "=r"(a) : "l"(p));
    return a;
}
__device__ __forceinline__ void ldsm4(uint32_t* r, uint32_t a) {
    asm volatile("ldmatrix.sync.aligned.m8n8.x4.shared.b16 {%0,%1,%2,%3}, [%4];"
                 : "=r"(r[0]), "=r"(r[1]), "=r"(r[2]), "=r"(r[3]) : "r"(a));
}
__device__ __forceinline__ void ldsm4t(uint32_t* r, uint32_t a) {
    asm volatile("ldmatrix.sync.aligned.m8n8.x4.trans.shared.b16 {%0,%1,%2,%3}, [%4];"
                 : "=r"(r[0]), "=r"(r[1]), "=r"(r[2]), "=r"(r[3]) : "r"(a));
}
__device__ __forceinline__ void mma16816(float* d, const uint32_t* a, const uint32_t* b) {
    asm volatile("mma.sync.aligned.m16n8k16.row.col.f32.f16.f16.f32 "
                 "{%0,%1,%2,%3}, {%4,%5,%6,%7}, {%8,%9}, {%0,%1,%2,%3};"
                 : "+f"(d[0]), "+f"(d[1]), "+f"(d[2]), "+f"(d[3])
                 : "r"(a[0]), "r"(a[1]), "r"(a[2]), "r"(a[3]), "r"(b[0]), "r"(b[1]));
}
__device__ __forceinline__ uint32_t pack_h2(float x0, float x1) {
    uint32_t r;
    asm("cvt.rn.f16x2.f32 %0, %1, %2;" : "=r"(r) : "f"(x1), "f"(x0));
    return r;
}
__device__ __forceinline__ float2 unpack_h2(uint32_t v) {
    return __half22float2(*reinterpret_cast<__half2*>(&v));
}

// ---------------- precompute ----------------
__global__ void precompute_kernel(const float* __restrict__ lam,
                                  const float* __restrict__ U,
                                  const float* __restrict__ V,
                                  const float* __restrict__ listT) {
    int tid = threadIdx.x;
    if (blockIdx.x < 64) {
        int e = blockIdx.x * 256 + tid;
        int c = e >> 7, k = e & 127;
        float s0 = 0.f, s1 = 0.f;
        #pragma unroll 8
        for (int r = 0; r < 64; r += 2) {
            s0 += U[c * 64 + r] * V[r * C_DIM + k];
            s1 += U[c * 64 + r + 1] * V[(r + 1) * C_DIM + k];
        }
        g_M[e] = s0 + s1;
    } else {
        int idx = (blockIdx.x - 64) * 256 + tid;
        if (idx < B_DIM * L_DIM * C_DIM) {
            int c = idx & 127;
            int t = (idx >> 7) % L_DIM;
            int b = idx / (L_DIM * C_DIM);
            float sp = log1pf(expf(lam[c]));
            g_decay[idx] = expf(-sp * listT[b * L_DIM + t]);
        }
    }
}

// single-pass fp16 GEMM, k=128: acc[2][4][4] += A[m0..+32][k] * B[k][n0..+32]
__device__ __forceinline__ void gemm128(uint32_t aB, uint32_t bB,
                                        int m0, int n0, int lane,
                                        float acc[2][4][4]) {
    const int arow = lane & 15;
    const int aq   = lane >> 4;
    #pragma unroll
    for (int k = 0; k < 128; k += 16) {
        uint32_t ah[2][4];
        #pragma unroll
        for (int mt = 0; mt < 2; ++mt) {
            uint32_t addr = aB + (uint32_t)((m0 + mt * 16 + arow) * ROWW + k * 2 + aq * 16);
            ldsm4(ah[mt], addr);
        }
        #pragma unroll
        for (int ng = 0; ng < 2; ++ng) {
            uint32_t addr = bB + (uint32_t)((k + arow) * ROWX + (n0 + ng * 16) * 2 + aq * 16);
            uint32_t bv[4];
            ldsm4t(bv, addr);
            #pragma unroll
            for (int hh = 0; hh < 2; ++hh) {
                const int nt = ng * 2 + hh;
                mma16816(acc[0][nt], ah[0], bv + hh * 2);
                mma16816(acc[1][nt], ah[1], bv + hh * 2);
            }
        }
    }
}

// ---------------- main kernel: 256 threads, 64 spatial cols, 2 CTAs/SM ----------------
__global__ __launch_bounds__(NTHREADS, 2)
void recurrent_kernel(const float* __restrict__ x,
                      const float* __restrict__ h0,
                      const float* __restrict__ Wout,
                      float* __restrict__ out,
                      float* __restrict__ hfin) {
    extern __shared__ char smem[];
    const uint32_t sb = smem_u32(smem);

    const int tid  = threadIdx.x;
    const int lane = tid & 31;
    const int wid  = tid >> 5;            // 0..7
    const int b    = blockIdx.x >> 6;     // 64 CTAs per batch
    const int s0   = (blockIdx.x & 63) * 64;
    const int wm   = wid & 3;
    const int wn   = wid >> 2;            // 0..1
    const int m0   = wm * 32;
    const int n0   = wn * 32;
    const int g    = lane >> 2;
    const int tq   = lane & 3;
    const size_t rstride = (size_t)L_DIM * HW_DIM;

    // staging coords: row = it*16 + (tid>>4), float4 col = tid & 15
    const int sr  = tid >> 4;       // 0..15
    const int sc4 = tid & 15;       // 0..15 (64 floats per row)

    // ---- stationary weights (fp16) ----
    for (int e = tid; e < C_DIM * C_DIM; e += NTHREADS) {
        int r = e >> 7, k = e & 127;
        uint32_t off = (uint32_t)(r * ROWW + k * 2);
        *(__half*)(smem + SM_M + off) = __float2half_rn(g_M[e]);
        *(__half*)(smem + SM_W + off) = __float2half_rn(Wout[e]);
    }

    // ---- initial hidden state fragments ----
    float h[2][4][4];
    #pragma unroll
    for (int mt = 0; mt < 2; ++mt) {
        #pragma unroll
        for (int nt = 0; nt < 4; ++nt) {
            int c_lo = m0 + mt * 16 + g;
            int s    = s0 + n0 + nt * 8 + tq * 2;
            float2 v0 = *(const float2*)&h0[(size_t)(b * C_DIM + c_lo) * HW_DIM + s];
            float2 v1 = *(const float2*)&h0[(size_t)(b * C_DIM + c_lo + 8) * HW_DIM + s];
            h[mt][nt][0] = v0.x; h[mt][nt][1] = v0.y;
            h[mt][nt][2] = v1.x; h[mt][nt][3] = v1.y;
        }
    }

    __syncthreads();  // weights ready

    for (int t = 0; t < L_DIM; ++t) {
        // ---- stage x(t): gmem fp32 -> f16 into BX (co-resident CTA hides LDG) ----
        #pragma unroll
        for (int it = 0; it < 8; ++it) {
            int r = it * 16 + sr;
            float4 v = *(const float4*)(x + ((size_t)(b * C_DIM + r) * L_DIM + t) * HW_DIM
                                          + s0 + sc4 * 4);
            *(uint2*)(smem + SM_BX + (uint32_t)(r * ROWX + sc4 * 8)) =
                make_uint2(pack_h2(v.x, v.y), pack_h2(v.z, v.w));
        }
        __syncthreads();

        // ---- GEMM1: u = M @ x ----
        float acc[2][4][4];
        #pragma unroll
        for (int mt = 0; mt < 2; ++mt)
            #pragma unroll
            for (int nt = 0; nt < 4; ++nt)
                #pragma unroll
                for (int q = 0; q < 4; ++q) acc[mt][nt][q] = 0.f;
        gemm128(sb + SM_M, sb + SM_BX, m0, n0, lane, acc);

        // ---- recurrence: h = decay(c)*h + u ----
        {
            const float* dk = &g_decay[(b * L_DIM + t) * C_DIM];
            #pragma unroll
            for (int mt = 0; mt < 2; ++mt) {
                float dA = __ldg(&dk[m0 + mt * 16 + g]);
                float dB = __ldg(&dk[m0 + mt * 16 + 8 + g]);
                #pragma unroll
                for (int nt = 0; nt < 4; ++nt) {
                    h[mt][nt][0] = dA * h[mt][nt][0] + acc[mt][nt][0];
                    h[mt][nt][1] = dA * h[mt][nt][1] + acc[mt][nt][1];
                    h[mt][nt][2] = dB * h[mt][nt][2] + acc[mt][nt][2];
                    h[mt][nt][3] = dB * h[mt][nt][3] + acc[mt][nt][3];
                }
            }
        }

        // ---- residual x from BX (fp16 hi-only) into GEMM2 accumulators ----
        #pragma unroll
        for (int mt = 0; mt < 2; ++mt) {
            #pragma unroll
            for (int nt = 0; nt < 4; ++nt) {
                int c_lo = m0 + mt * 16 + g;
                int cb   = (n0 + nt * 8 + tq * 2) * 2;
                float2 r0 = unpack_h2(*(const uint32_t*)(smem + SM_BX + (uint32_t)(c_lo * ROWX + cb)));
                float2 r1 = unpack_h2(*(const uint32_t*)(smem + SM_BX + (uint32_t)((c_lo + 8) * ROWX + cb)));
                acc[mt][nt][0] = r0.x; acc[mt][nt][1] = r0.y;
                acc[mt][nt][2] = r1.x; acc[mt][nt][3] = r1.y;
            }
        }

        // ---- write h (f16) into BH for GEMM2 ----
        #pragma unroll
        for (int mt = 0; mt < 2; ++mt) {
            #pragma unroll
            for (int nt = 0; nt < 4; ++nt) {
                int c_lo = m0 + mt * 16 + g;
                int cb   = (n0 + nt * 8 + tq * 2) * 2;
                *(uint32_t*)(smem + SM_BH + (uint32_t)(c_lo * ROWX + cb)) =
                    pack_h2(h[mt][nt][0], h[mt][nt][1]);
                *(uint32_t*)(smem + SM_BH + (uint32_t)((c_lo + 8) * ROWX + cb)) =
                    pack_h2(h[mt][nt][2], h[mt][nt][3]);
            }
        }
        __syncthreads();

        // ---- GEMM2: out = x + Wout @ h ----
        gemm128(sb + SM_W, sb + SM_BH, m0, n0, lane, acc);

        // ---- store output ----
        #pragma unroll
        for (int mt = 0; mt < 2; ++mt) {
            #pragma unroll
            for (int nt = 0; nt < 4; ++nt) {
                int d_lo = m0 + mt * 16 + g;
                float* po = out + ((size_t)(b * C_DIM + d_lo) * L_DIM + t) * HW_DIM
                                + s0 + n0 + nt * 8 + tq * 2;
                *(float2*)po = make_float2(acc[mt][nt][0], acc[mt][nt][1]);
                *(float2*)(po + 8 * rstride) = make_float2(acc[mt][nt][2], acc[mt][nt][3]);
            }
        }
        __syncthreads();   // BX/BH reads done before next staging / h-write
    }

    // ---- final hidden state ----
    #pragma unroll
    for (int mt = 0; mt < 2; ++mt) {
        #pragma unroll
        for (int nt = 0; nt < 4; ++nt) {
            int c_lo = m0 + mt * 16 + g;
            int s    = s0 + n0 + nt * 8 + tq * 2;
            *(float2*)&hfin[(size_t)(b * C_DIM + c_lo) * HW_DIM + s] =
                make_float2(h[mt][nt][0], h[mt][nt][1]);
            *(float2*)&hfin[(size_t)(b * C_DIM + c_lo + 8) * HW_DIM + s] =
                make_float2(h[mt][nt][2], h[mt][nt][3]);
        }
    }
}

extern "C" void kernel_launch(void* const* d_in, const int* in_sizes, int n_in,
                              void* d_out, int out_size) {
    const float* x     = (const float*)d_in[0];
    const float* h0    = (const float*)d_in[1];
    const float* listT = (const float*)d_in[2];
    const float* lam   = (const float*)d_in[3];
    const float* U     = (const float*)d_in[4];
    const float* V     = (const float*)d_in[5];
    const float* Wout  = (const float*)d_in[6];

    float* out  = (float*)d_out;
    float* hfin = out + (size_t)B_DIM * C_DIM * L_DIM * HW_DIM;

    precompute_kernel<<<112, 256>>>(lam, U, V, listT);

    cudaFuncSetAttribute(recurrent_kernel,
                         cudaFuncAttributeMaxDynamicSharedMemorySize, SMEM_BYTES);
    recurrent_kernel<<<B_DIM * (HW_DIM / 64), NTHREADS, SMEM_BYTES>>>(x, h0, Wout, out, hfin);
}